// round 8
// baseline (speedup 1.0000x reference)
#include <cuda_runtime.h>
#include <math.h>

#define SEQ   2048
#define DM    768
#define NH    12
#define DK    64
#define BATCH 4
#define MTOT  (BATCH*SEQ)   // 8192

// Qt[64][132] + Kt[64][68] + Vs[64][68] + Ps[128][68], fp32
#define ATTN_SMEM ((64*132 + 64*68 + 64*68 + 128*68)*4)   // 103424 B

typedef unsigned long long u64;

// ---- packed f32x2 helpers (sm_103a FFMA2 path) ----------------------------
__device__ __forceinline__ u64 dup2(float x) {
    u64 r; unsigned u = __float_as_uint(x);
    asm("mov.b64 %0, {%1, %1};" : "=l"(r) : "r"(u));
    return r;
}
__device__ __forceinline__ void fma2(u64& d, u64 a, u64 b) {
    asm("fma.rn.f32x2 %0, %1, %2, %0;" : "+l"(d) : "l"(a), "l"(b));
}
__device__ __forceinline__ void mul2(u64& d, u64 a) {
    asm("mul.rn.f32x2 %0, %0, %1;" : "+l"(d) : "l"(a));
}
__device__ __forceinline__ float2 unp2(u64 v) {
    unsigned lo, hi;
    asm("mov.b64 {%0, %1}, %2;" : "=r"(lo), "=r"(hi) : "l"(v));
    return make_float2(__uint_as_float(lo), __uint_as_float(hi));
}

// Scratch (allocation-free rule: __device__ globals)
__device__ float g_Q[BATCH*NH*SEQ*DK];
__device__ float g_K[BATCH*NH*SEQ*DK];
__device__ float g_V[BATCH*NH*SEQ*DK];
__device__ float g_ctx[MTOT*DM];

// ---------------------------------------------------------------------------
// Shared GEMM body: out = A @ W^T + bias.
// BM=BN=128, BK=8, 256 threads, 8x8 microtile via f32x2 (acc paired along j),
// double-buffered smem, vectorized float4 epilogue with hoisted bias.
// ---------------------------------------------------------------------------
template<bool HEAD_LAYOUT>
__device__ __forceinline__ void gemm_body(
    const float* __restrict__ A,
    const float* __restrict__ W,
    const float* __restrict__ bias,
    float* __restrict__ out,
    int mb, int nb,
    float As[2][8*132], float Bs[2][8*132])
{
    const int tid = threadIdx.x;
    const int tx  = tid & 15;
    const int ty  = tid >> 4;
    const int lrow = tid >> 1;
    const int lk   = (tid & 1) * 4;

    const float* Aptr = A + (size_t)(mb + lrow) * DM + lk;
    const float* Bptr = W + (size_t)(nb + lrow) * DM + lk;

    u64 acc2[8][4] = {};   // [i][jp]: pair = (acc[i][2jp], acc[i][2jp+1])

    {
        float4 av = *(const float4*)(Aptr);
        float4 bv = *(const float4*)(Bptr);
        As[0][(lk+0)*132 + lrow] = av.x;
        As[0][(lk+1)*132 + lrow] = av.y;
        As[0][(lk+2)*132 + lrow] = av.z;
        As[0][(lk+3)*132 + lrow] = av.w;
        Bs[0][(lk+0)*132 + lrow] = bv.x;
        Bs[0][(lk+1)*132 + lrow] = bv.y;
        Bs[0][(lk+2)*132 + lrow] = bv.z;
        Bs[0][(lk+3)*132 + lrow] = bv.w;
    }
    __syncthreads();

    int buf = 0;
    for (int k0 = 0; k0 < DM; k0 += 8) {
        float4 av, bv;
        const bool more = (k0 + 8 < DM);
        if (more) {                       // prefetch next tile (overlaps compute)
            av = *(const float4*)(Aptr + k0 + 8);
            bv = *(const float4*)(Bptr + k0 + 8);
        }

        #pragma unroll
        for (int kk = 0; kk < 8; kk++) {
            float4 a0 = *(const float4*)&As[buf][kk*132 + 4*ty];
            float4 a1 = *(const float4*)&As[buf][kk*132 + 64 + 4*ty];
            // b pairs come free: reinterpret LDS.128 as two f32x2
            ulonglong2 b0 = *(const ulonglong2*)&Bs[buf][kk*132 + 4*tx];
            ulonglong2 b1 = *(const ulonglong2*)&Bs[buf][kk*132 + 64 + 4*tx];
            u64 bp[4] = {b0.x, b0.y, b1.x, b1.y};
            float ar[8] = {a0.x, a0.y, a0.z, a0.w, a1.x, a1.y, a1.z, a1.w};
            #pragma unroll
            for (int i = 0; i < 8; i++) {
                u64 ad = dup2(ar[i]);     // ALU pipe, hides in spare slots
                #pragma unroll
                for (int p = 0; p < 4; p++)
                    fma2(acc2[i][p], ad, bp[p]);
            }
        }

        if (more) {
            const int nb2 = buf ^ 1;
            As[nb2][(lk+0)*132 + lrow] = av.x;
            As[nb2][(lk+1)*132 + lrow] = av.y;
            As[nb2][(lk+2)*132 + lrow] = av.z;
            As[nb2][(lk+3)*132 + lrow] = av.w;
            Bs[nb2][(lk+0)*132 + lrow] = bv.x;
            Bs[nb2][(lk+1)*132 + lrow] = bv.y;
            Bs[nb2][(lk+2)*132 + lrow] = bv.z;
            Bs[nb2][(lk+3)*132 + lrow] = bv.w;
            __syncthreads();
            buf = nb2;
        }
    }

    // epilogue: hoisted bias, vectorized STG.128
    const int gn0 = nb + 4*tx;
    const int gn1 = nb + 64 + 4*tx;
    const float4 bi0 = *(const float4*)&bias[gn0];
    const float4 bi1 = *(const float4*)&bias[gn1];

    #pragma unroll
    for (int i = 0; i < 8; i++) {
        int gm = mb + ((i < 4) ? (4*ty + i) : (64 + 4*ty + i - 4));
        float2 p0 = unp2(acc2[i][0]);
        float2 p1 = unp2(acc2[i][1]);
        float2 p2 = unp2(acc2[i][2]);
        float2 p3 = unp2(acc2[i][3]);
        float4 v0 = make_float4(p0.x+bi0.x, p0.y+bi0.y, p1.x+bi0.z, p1.y+bi0.w);
        float4 v1 = make_float4(p2.x+bi1.x, p2.y+bi1.y, p3.x+bi1.z, p3.y+bi1.w);
        if (HEAD_LAYOUT) {
            int bb = gm >> 11;          // gm / SEQ
            int ss = gm & 2047;         // gm % SEQ
            *(float4*)&out[((size_t)(bb*NH + (gn0>>6))*SEQ + ss)*DK + (gn0&63)] = v0;
            *(float4*)&out[((size_t)(bb*NH + (gn1>>6))*SEQ + ss)*DK + (gn1&63)] = v1;
        } else {
            *(float4*)&out[(size_t)gm * DM + gn0] = v0;
            *(float4*)&out[(size_t)gm * DM + gn1] = v1;
        }
    }
}

template<bool HEAD_LAYOUT>
__global__ __launch_bounds__(256) void gemm_kernel(
    const float* __restrict__ A,
    const float* __restrict__ W,
    const float* __restrict__ bias,
    float* __restrict__ out)
{
    __shared__ float As[2][8*132];
    __shared__ float Bs[2][8*132];
    gemm_body<HEAD_LAYOUT>(A, W, bias, out,
                           blockIdx.y * 128, blockIdx.x * 128, As, Bs);
}

// Fused QKV projection: blockIdx.z selects (W,b,out); x tiles reused via L2.
__global__ __launch_bounds__(256) void qkv_kernel(
    const float* __restrict__ A,
    const float* __restrict__ w_q, const float* __restrict__ b_q, float* __restrict__ o_q,
    const float* __restrict__ w_k, const float* __restrict__ b_k, float* __restrict__ o_k,
    const float* __restrict__ w_v, const float* __restrict__ b_v, float* __restrict__ o_v)
{
    __shared__ float As[2][8*132];
    __shared__ float Bs[2][8*132];

    const float* W;  const float* bias;  float* out;
    if      (blockIdx.z == 0) { W = w_q; bias = b_q; out = o_q; }
    else if (blockIdx.z == 1) { W = w_k; bias = b_k; out = o_k; }
    else                      { W = w_v; bias = b_v; out = o_v; }

    gemm_body<true>(A, W, bias, out,
                    blockIdx.y * 128, blockIdx.x * 128, As, Bs);
}

// ---------------------------------------------------------------------------
// Flash attention, causal. Br=128, Bc=64, 256 threads, 8x4 microtile via
// f32x2. Software-pipelined K/V prefetch; 1/sqrt(dk)=2^-3 folded into Q at
// load (bit-exact power-of-two scale); PV loop chunked by 4 columns so P
// loads amortize as LDS.128.
// ---------------------------------------------------------------------------
__global__ __launch_bounds__(256, 2) void attn_kernel()
{
    extern __shared__ float sm[];
    float* Qt = sm;                        // [64 k][132]: Qt[k][r] = Q[r][k]*0.125
    float* Kt = Qt + 64*132;               // [64 k][68]:  Kt[k][c] = K[c][k]
    float* Vs = Kt + 64*68;                // [64 c][68]:  Vs[c][d]
    float* Ps = Vs + 64*68;                // [128 r][68]: Ps[r][c]

    const int qb   = (SEQ/128 - 1) - (int)blockIdx.x;  // big blocks first
    const int h    = blockIdx.y;
    const int b    = blockIdx.z;
    const int tid  = threadIdx.x;
    const int tx   = tid & 15;   // kv col group (S) / dk group (O)
    const int ty   = tid >> 4;   // q row group (8 rows)

    const size_t head_off = ((size_t)b*NH + h) * SEQ * DK;
    const float* Qg = g_Q + head_off;
    const float* Kg = g_K + head_off;
    const float* Vg = g_V + head_off;

    const int qbase = qb * 128;

    // per-thread K/V smem coords (64-row tiles)
    int rr[4], cc[4];
    #pragma unroll
    for (int i = 0; i < 4; i++) {
        int idx = tid + i*256;
        rr[i] = idx >> 4;             // 0..63
        cc[i] = (idx & 15) * 4;       // 0..60
    }

    // Load Q tile (128 rows), transposed into Qt, pre-scaled by 2^-3
    // (exact in fp32: exponent shift only, so S = (Q*s)K^T == (QK^T)*s bitwise)
    #pragma unroll
    for (int i = 0; i < 8; i++) {
        int idx = tid + i*256;        // 0..2047
        int r   = idx >> 4;           // 0..127
        int c   = (idx & 15) * 4;     // 0..60
        float4 v = *(const float4*)&Qg[(size_t)(qbase + r)*DK + c];
        Qt[(c+0)*132 + r] = v.x * 0.125f;
        Qt[(c+1)*132 + r] = v.y * 0.125f;
        Qt[(c+2)*132 + r] = v.z * 0.125f;
        Qt[(c+3)*132 + r] = v.w * 0.125f;
    }

    u64 o2[8][2] = {};                 // [ii][jp]: pair = (o[ii][2jp], o[ii][2jp+1])
    float mrow[8], lrow[8];
    #pragma unroll
    for (int i = 0; i < 8; i++) { mrow[i] = -INFINITY; lrow[i] = 0.0f; }

    const int jmax = 2*qb + 1;

    // pipeline prologue: K/V tile 0 into registers
    float4 kreg[4], vreg[4];
    #pragma unroll
    for (int i = 0; i < 4; i++) {
        kreg[i] = *(const float4*)&Kg[(size_t)(rr[i])*DK + cc[i]];
        vreg[i] = *(const float4*)&Vg[(size_t)(rr[i])*DK + cc[i]];
    }

    for (int j = 0; j <= jmax; j++) {
        const int kb = j * 64;

        __syncthreads();   // previous iteration's K/V (and Ps) reads done
        #pragma unroll
        for (int i = 0; i < 4; i++) {
            Kt[(cc[i]+0)*68 + rr[i]] = kreg[i].x;
            Kt[(cc[i]+1)*68 + rr[i]] = kreg[i].y;
            Kt[(cc[i]+2)*68 + rr[i]] = kreg[i].z;
            Kt[(cc[i]+3)*68 + rr[i]] = kreg[i].w;
            *(float4*)&Vs[rr[i]*68 + cc[i]] = vreg[i];
        }
        __syncthreads();

        // prefetch next K/V tile: latency hides under S + softmax + PV
        if (j < jmax) {
            const int kb2 = kb + 64;
            #pragma unroll
            for (int i = 0; i < 4; i++) {
                kreg[i] = *(const float4*)&Kg[(size_t)(kb2 + rr[i])*DK + cc[i]];
                vreg[i] = *(const float4*)&Vg[(size_t)(kb2 + rr[i])*DK + cc[i]];
            }
        }

        // S = (Q*2^-3) K^T  (128x64x64): FFMA2, K pairs free, Q dup on ALU
        u64 s2[8][2] = {};
        #pragma unroll 4
        for (int kk = 0; kk < 64; kk++) {
            float4 a0 = *(const float4*)&Qt[kk*132 + 8*ty];
            float4 a1 = *(const float4*)&Qt[kk*132 + 8*ty + 4];
            ulonglong2 kp = *(const ulonglong2*)&Kt[kk*68 + 4*tx];
            float ar[8] = {a0.x, a0.y, a0.z, a0.w, a1.x, a1.y, a1.z, a1.w};
            #pragma unroll
            for (int ii = 0; ii < 8; ii++) {
                u64 qd = dup2(ar[ii]);
                fma2(s2[ii][0], qd, kp.x);
                fma2(s2[ii][1], qd, kp.y);
            }
        }

        // causal mask (diagonal blocks only) + online softmax
        const bool domask = (j >= 2*qb);
        #pragma unroll
        for (int ii = 0; ii < 8; ii++) {
            float2 sa = unp2(s2[ii][0]);
            float2 sb = unp2(s2[ii][1]);
            float s[4] = {sa.x, sa.y, sb.x, sb.y};
            const int qr = qbase + 8*ty + ii;
            float mt = -INFINITY;
            #pragma unroll
            for (int jj = 0; jj < 4; jj++) {
                float sv = s[jj];
                if (domask && (kb + 4*tx + jj > qr)) sv = -INFINITY;
                s[jj] = sv;
                mt = fmaxf(mt, sv);
            }
            #pragma unroll
            for (int off = 1; off < 16; off <<= 1)
                mt = fmaxf(mt, __shfl_xor_sync(0xffffffffu, mt, off));
            float mnew  = fmaxf(mrow[ii], mt);
            float alpha = (mrow[ii] == -INFINITY) ? 0.0f : __expf(mrow[ii] - mnew);
            float lt = 0.0f;
            #pragma unroll
            for (int jj = 0; jj < 4; jj++) {
                float p = __expf(s[jj] - mnew);
                s[jj] = p;
                lt += p;
            }
            #pragma unroll
            for (int off = 1; off < 16; off <<= 1)
                lt += __shfl_xor_sync(0xffffffffu, lt, off);
            lrow[ii] = lrow[ii]*alpha + lt;
            mrow[ii] = mnew;
            u64 ad = dup2(alpha);
            mul2(o2[ii][0], ad);
            mul2(o2[ii][1], ad);
            // stash P row-major, vectorized (conflict-free STS.128)
            *(float4*)&Ps[(8*ty+ii)*68 + 4*tx] = make_float4(s[0], s[1], s[2], s[3]);
        }
        __syncthreads();

        // O += P @ V  (128x64x64): c chunked by 4 so P loads are LDS.128
        #pragma unroll 2
        for (int c0 = 0; c0 < 64; c0 += 4) {
            ulonglong2 vp[4];
            #pragma unroll
            for (int q = 0; q < 4; q++)
                vp[q] = *(const ulonglong2*)&Vs[(c0+q)*68 + 4*tx];
            #pragma unroll
            for (int ii = 0; ii < 8; ii++) {
                float4 p4 = *(const float4*)&Ps[(8*ty+ii)*68 + c0];
                float pr[4] = {p4.x, p4.y, p4.z, p4.w};
                #pragma unroll
                for (int q = 0; q < 4; q++) {
                    u64 pd = dup2(pr[q]);
                    fma2(o2[ii][0], pd, vp[q].x);
                    fma2(o2[ii][1], pd, vp[q].y);
                }
            }
        }
    }

    // normalize + write back into [b, s, d] interleaved layout
    #pragma unroll
    for (int ii = 0; ii < 8; ii++) {
        float inv = 1.0f / lrow[ii];
        int qr = qbase + 8*ty + ii;
        float2 oa = unp2(o2[ii][0]);
        float2 ob = unp2(o2[ii][1]);
        float* dst = g_ctx + ((size_t)(b*SEQ + qr))*DM + h*DK + 4*tx;
        *(float4*)dst = make_float4(oa.x*inv, oa.y*inv, ob.x*inv, ob.y*inv);
    }
}

// ---------------------------------------------------------------------------
extern "C" void kernel_launch(void* const* d_in, const int* in_sizes, int n_in,
                              void* d_out, int out_size)
{
    const float* x  = (const float*)d_in[0];
    const float* wq = (const float*)d_in[1];
    const float* bq = (const float*)d_in[2];
    const float* wk = (const float*)d_in[3];
    const float* bk = (const float*)d_in[4];
    const float* wv = (const float*)d_in[5];
    const float* bv = (const float*)d_in[6];
    const float* wo = (const float*)d_in[7];
    const float* bo = (const float*)d_in[8];

    float *qp, *kp, *vp, *cp;
    cudaGetSymbolAddress((void**)&qp, g_Q);
    cudaGetSymbolAddress((void**)&kp, g_K);
    cudaGetSymbolAddress((void**)&vp, g_V);
    cudaGetSymbolAddress((void**)&cp, g_ctx);

    cudaFuncSetAttribute(attn_kernel,
                         cudaFuncAttributeMaxDynamicSharedMemorySize, ATTN_SMEM);

    dim3 gq(DM/128, MTOT/128, 3);   // fused Q/K/V
    qkv_kernel<<<gq, 256>>>(x, wq, bq, qp, wk, bk, kp, wv, bv, vp);
    attn_kernel<<<dim3(SEQ/128, NH, BATCH), 256, ATTN_SMEM>>>();
    dim3 gg(DM/128, MTOT/128);
    gemm_kernel<false><<<gg, 256>>>(cp, wo, bo, (float*)d_out);
}

// round 15
// speedup vs baseline: 1.0322x; 1.0322x over previous
#include <cuda_runtime.h>
#include <math.h>

#define SEQ   2048
#define DM    768
#define NH    12
#define DK    64
#define BATCH 4
#define MTOT  (BATCH*SEQ)   // 8192

// Qt[64][132] + Kt[64][68] + Vs[64][68] + Ps[128][68], fp32
#define ATTN_SMEM ((64*132 + 64*68 + 64*68 + 128*68)*4)   // 103424 B

typedef unsigned long long u64;

// ---- packed f32x2 helpers (sm_103a FFMA2 path) ----------------------------
__device__ __forceinline__ u64 dup2(float x) {
    u64 r; unsigned u = __float_as_uint(x);
    asm("mov.b64 %0, {%1, %1};" : "=l"(r) : "r"(u));
    return r;
}
__device__ __forceinline__ void fma2(u64& d, u64 a, u64 b) {
    asm("fma.rn.f32x2 %0, %1, %2, %0;" : "+l"(d) : "l"(a), "l"(b));
}
__device__ __forceinline__ void mul2(u64& d, u64 a) {
    asm("mul.rn.f32x2 %0, %0, %1;" : "+l"(d) : "l"(a));
}
__device__ __forceinline__ float2 unp2(u64 v) {
    unsigned lo, hi;
    asm("mov.b64 {%0, %1}, %2;" : "=r"(lo), "=r"(hi) : "l"(v));
    return make_float2(__uint_as_float(lo), __uint_as_float(hi));
}

// Scratch (allocation-free rule: __device__ globals)
__device__ float g_Q[BATCH*NH*SEQ*DK];
__device__ float g_K[BATCH*NH*SEQ*DK];
__device__ float g_V[BATCH*NH*SEQ*DK];
__device__ float g_ctx[MTOT*DM];

// ---------------------------------------------------------------------------
// Shared GEMM body: out = A @ W^T + bias.
// BM=BN=128, BK=8, 256 threads, 8x8 microtile via f32x2 (acc paired along j),
// double-buffered smem, vectorized float4 epilogue with hoisted bias.
// ---------------------------------------------------------------------------
template<bool HEAD_LAYOUT>
__device__ __forceinline__ void gemm_body(
    const float* __restrict__ A,
    const float* __restrict__ W,
    const float* __restrict__ bias,
    float* __restrict__ out,
    int mb, int nb,
    float As[2][8*132], float Bs[2][8*132])
{
    const int tid = threadIdx.x;
    const int tx  = tid & 15;
    const int ty  = tid >> 4;
    const int lrow = tid >> 1;
    const int lk   = (tid & 1) * 4;

    const float* Aptr = A + (size_t)(mb + lrow) * DM + lk;
    const float* Bptr = W + (size_t)(nb + lrow) * DM + lk;

    u64 acc2[8][4] = {};   // [i][jp]: pair = (acc[i][2jp], acc[i][2jp+1])

    {
        float4 av = *(const float4*)(Aptr);
        float4 bv = *(const float4*)(Bptr);
        As[0][(lk+0)*132 + lrow] = av.x;
        As[0][(lk+1)*132 + lrow] = av.y;
        As[0][(lk+2)*132 + lrow] = av.z;
        As[0][(lk+3)*132 + lrow] = av.w;
        Bs[0][(lk+0)*132 + lrow] = bv.x;
        Bs[0][(lk+1)*132 + lrow] = bv.y;
        Bs[0][(lk+2)*132 + lrow] = bv.z;
        Bs[0][(lk+3)*132 + lrow] = bv.w;
    }
    __syncthreads();

    int buf = 0;
    for (int k0 = 0; k0 < DM; k0 += 8) {
        float4 av, bv;
        const bool more = (k0 + 8 < DM);
        if (more) {                       // prefetch next tile (overlaps compute)
            av = *(const float4*)(Aptr + k0 + 8);
            bv = *(const float4*)(Bptr + k0 + 8);
        }

        #pragma unroll
        for (int kk = 0; kk < 8; kk++) {
            float4 a0 = *(const float4*)&As[buf][kk*132 + 4*ty];
            float4 a1 = *(const float4*)&As[buf][kk*132 + 64 + 4*ty];
            // b pairs come free: reinterpret LDS.128 as two f32x2
            ulonglong2 b0 = *(const ulonglong2*)&Bs[buf][kk*132 + 4*tx];
            ulonglong2 b1 = *(const ulonglong2*)&Bs[buf][kk*132 + 64 + 4*tx];
            u64 bp[4] = {b0.x, b0.y, b1.x, b1.y};
            float ar[8] = {a0.x, a0.y, a0.z, a0.w, a1.x, a1.y, a1.z, a1.w};
            #pragma unroll
            for (int i = 0; i < 8; i++) {
                u64 ad = dup2(ar[i]);     // ALU pipe, hides in spare slots
                #pragma unroll
                for (int p = 0; p < 4; p++)
                    fma2(acc2[i][p], ad, bp[p]);
            }
        }

        if (more) {
            const int nb2 = buf ^ 1;
            As[nb2][(lk+0)*132 + lrow] = av.x;
            As[nb2][(lk+1)*132 + lrow] = av.y;
            As[nb2][(lk+2)*132 + lrow] = av.z;
            As[nb2][(lk+3)*132 + lrow] = av.w;
            Bs[nb2][(lk+0)*132 + lrow] = bv.x;
            Bs[nb2][(lk+1)*132 + lrow] = bv.y;
            Bs[nb2][(lk+2)*132 + lrow] = bv.z;
            Bs[nb2][(lk+3)*132 + lrow] = bv.w;
            __syncthreads();
            buf = nb2;
        }
    }

    // epilogue: hoisted bias, vectorized STG.128
    const int gn0 = nb + 4*tx;
    const int gn1 = nb + 64 + 4*tx;
    const float4 bi0 = *(const float4*)&bias[gn0];
    const float4 bi1 = *(const float4*)&bias[gn1];

    #pragma unroll
    for (int i = 0; i < 8; i++) {
        int gm = mb + ((i < 4) ? (4*ty + i) : (64 + 4*ty + i - 4));
        float2 p0 = unp2(acc2[i][0]);
        float2 p1 = unp2(acc2[i][1]);
        float2 p2 = unp2(acc2[i][2]);
        float2 p3 = unp2(acc2[i][3]);
        float4 v0 = make_float4(p0.x+bi0.x, p0.y+bi0.y, p1.x+bi0.z, p1.y+bi0.w);
        float4 v1 = make_float4(p2.x+bi1.x, p2.y+bi1.y, p3.x+bi1.z, p3.y+bi1.w);
        if (HEAD_LAYOUT) {
            int bb = gm >> 11;          // gm / SEQ
            int ss = gm & 2047;         // gm % SEQ
            *(float4*)&out[((size_t)(bb*NH + (gn0>>6))*SEQ + ss)*DK + (gn0&63)] = v0;
            *(float4*)&out[((size_t)(bb*NH + (gn1>>6))*SEQ + ss)*DK + (gn1&63)] = v1;
        } else {
            *(float4*)&out[(size_t)gm * DM + gn0] = v0;
            *(float4*)&out[(size_t)gm * DM + gn1] = v1;
        }
    }
}

// 2 CTAs/SM (caps regs at 128; R8 ncu: 134 regs -> occ 12.5%, issue 46.2%)
template<bool HEAD_LAYOUT>
__global__ __launch_bounds__(256, 2) void gemm_kernel(
    const float* __restrict__ A,
    const float* __restrict__ W,
    const float* __restrict__ bias,
    float* __restrict__ out)
{
    __shared__ float As[2][8*132];
    __shared__ float Bs[2][8*132];
    gemm_body<HEAD_LAYOUT>(A, W, bias, out,
                           blockIdx.y * 128, blockIdx.x * 128, As, Bs);
}

// Fused QKV projection: blockIdx.z selects (W,b,out); x tiles reused via L2.
__global__ __launch_bounds__(256, 2) void qkv_kernel(
    const float* __restrict__ A,
    const float* __restrict__ w_q, const float* __restrict__ b_q, float* __restrict__ o_q,
    const float* __restrict__ w_k, const float* __restrict__ b_k, float* __restrict__ o_k,
    const float* __restrict__ w_v, const float* __restrict__ b_v, float* __restrict__ o_v)
{
    __shared__ float As[2][8*132];
    __shared__ float Bs[2][8*132];

    const float* W;  const float* bias;  float* out;
    if      (blockIdx.z == 0) { W = w_q; bias = b_q; out = o_q; }
    else if (blockIdx.z == 1) { W = w_k; bias = b_k; out = o_k; }
    else                      { W = w_v; bias = b_v; out = o_v; }

    gemm_body<true>(A, W, bias, out,
                    blockIdx.y * 128, blockIdx.x * 128, As, Bs);
}

// ---------------------------------------------------------------------------
// Flash attention, causal. Br=128, Bc=64, 256 threads, 8x4 microtile via
// f32x2. Software-pipelined K/V prefetch; 1/sqrt(dk) folded into Q (exact
// power-of-two); PV P-loads amortized as LDS.128.
// Ps staging is WARP-LOCAL (rows 8*ty.. written+read by threads 16*ty..16*ty+15,
// one warp) -> post-softmax barrier is __syncwarp, not __syncthreads. Warps
// de-lockstep: one warp's softmax (MUFU/SHFL) overlaps another's PV (FFMA2).
// ---------------------------------------------------------------------------
__global__ __launch_bounds__(256, 2) void attn_kernel()
{
    extern __shared__ float sm[];
    float* Qt = sm;                        // [64 k][132]: Qt[k][r] = Q[r][k]*0.125
    float* Kt = Qt + 64*132;               // [64 k][68]:  Kt[k][c] = K[c][k]
    float* Vs = Kt + 64*68;                // [64 c][68]:  Vs[c][d]
    float* Ps = Vs + 64*68;                // [128 r][68]: Ps[r][c]

    const int qb   = (SEQ/128 - 1) - (int)blockIdx.x;  // big blocks first
    const int h    = blockIdx.y;
    const int b    = blockIdx.z;
    const int tid  = threadIdx.x;
    const int tx   = tid & 15;   // kv col group (S) / dk group (O)
    const int ty   = tid >> 4;   // q row group (8 rows)

    const size_t head_off = ((size_t)b*NH + h) * SEQ * DK;
    const float* Qg = g_Q + head_off;
    const float* Kg = g_K + head_off;
    const float* Vg = g_V + head_off;

    const int qbase = qb * 128;

    // per-thread K/V smem coords (64-row tiles)
    int rr[4], cc[4];
    #pragma unroll
    for (int i = 0; i < 4; i++) {
        int idx = tid + i*256;
        rr[i] = idx >> 4;             // 0..63
        cc[i] = (idx & 15) * 4;       // 0..60
    }

    // Load Q tile (128 rows), transposed into Qt, pre-scaled by 2^-3
    // (exact in fp32: exponent shift only, so S = (Q*s)K^T == (QK^T)*s bitwise)
    #pragma unroll
    for (int i = 0; i < 8; i++) {
        int idx = tid + i*256;        // 0..2047
        int r   = idx >> 4;           // 0..127
        int c   = (idx & 15) * 4;     // 0..60
        float4 v = *(const float4*)&Qg[(size_t)(qbase + r)*DK + c];
        Qt[(c+0)*132 + r] = v.x * 0.125f;
        Qt[(c+1)*132 + r] = v.y * 0.125f;
        Qt[(c+2)*132 + r] = v.z * 0.125f;
        Qt[(c+3)*132 + r] = v.w * 0.125f;
    }

    u64 o2[8][2] = {};                 // [ii][jp]: pair = (o[ii][2jp], o[ii][2jp+1])
    float mrow[8], lrow[8];
    #pragma unroll
    for (int i = 0; i < 8; i++) { mrow[i] = -INFINITY; lrow[i] = 0.0f; }

    const int jmax = 2*qb + 1;

    // pipeline prologue: K/V tile 0 into registers
    float4 kreg[4], vreg[4];
    #pragma unroll
    for (int i = 0; i < 4; i++) {
        kreg[i] = *(const float4*)&Kg[(size_t)(rr[i])*DK + cc[i]];
        vreg[i] = *(const float4*)&Vg[(size_t)(rr[i])*DK + cc[i]];
    }

    for (int j = 0; j <= jmax; j++) {
        const int kb = j * 64;

        __syncthreads();   // all warps done reading previous K/V (PV) and Qt
        #pragma unroll
        for (int i = 0; i < 4; i++) {
            Kt[(cc[i]+0)*68 + rr[i]] = kreg[i].x;
            Kt[(cc[i]+1)*68 + rr[i]] = kreg[i].y;
            Kt[(cc[i]+2)*68 + rr[i]] = kreg[i].z;
            Kt[(cc[i]+3)*68 + rr[i]] = kreg[i].w;
            *(float4*)&Vs[rr[i]*68 + cc[i]] = vreg[i];
        }
        __syncthreads();   // publish K/V to all warps

        // prefetch next K/V tile: latency hides under S + softmax + PV
        if (j < jmax) {
            const int kb2 = kb + 64;
            #pragma unroll
            for (int i = 0; i < 4; i++) {
                kreg[i] = *(const float4*)&Kg[(size_t)(kb2 + rr[i])*DK + cc[i]];
                vreg[i] = *(const float4*)&Vg[(size_t)(kb2 + rr[i])*DK + cc[i]];
            }
        }

        // S = (Q*2^-3) K^T  (128x64x64): FFMA2, K pairs free, Q dup on ALU
        u64 s2[8][2] = {};
        #pragma unroll 4
        for (int kk = 0; kk < 64; kk++) {
            float4 a0 = *(const float4*)&Qt[kk*132 + 8*ty];
            float4 a1 = *(const float4*)&Qt[kk*132 + 8*ty + 4];
            ulonglong2 kp = *(const ulonglong2*)&Kt[kk*68 + 4*tx];
            float ar[8] = {a0.x, a0.y, a0.z, a0.w, a1.x, a1.y, a1.z, a1.w};
            #pragma unroll
            for (int ii = 0; ii < 8; ii++) {
                u64 qd = dup2(ar[ii]);
                fma2(s2[ii][0], qd, kp.x);
                fma2(s2[ii][1], qd, kp.y);
            }
        }

        // causal mask (diagonal blocks only) + online softmax
        const bool domask = (j >= 2*qb);
        #pragma unroll
        for (int ii = 0; ii < 8; ii++) {
            float2 sa = unp2(s2[ii][0]);
            float2 sb = unp2(s2[ii][1]);
            float s[4] = {sa.x, sa.y, sb.x, sb.y};
            const int qr = qbase + 8*ty + ii;
            float mt = -INFINITY;
            #pragma unroll
            for (int jj = 0; jj < 4; jj++) {
                float sv = s[jj];
                if (domask && (kb + 4*tx + jj > qr)) sv = -INFINITY;
                s[jj] = sv;
                mt = fmaxf(mt, sv);
            }
            #pragma unroll
            for (int off = 1; off < 16; off <<= 1)
                mt = fmaxf(mt, __shfl_xor_sync(0xffffffffu, mt, off));
            float mnew  = fmaxf(mrow[ii], mt);
            float alpha = (mrow[ii] == -INFINITY) ? 0.0f : __expf(mrow[ii] - mnew);
            float lt = 0.0f;
            #pragma unroll
            for (int jj = 0; jj < 4; jj++) {
                float p = __expf(s[jj] - mnew);
                s[jj] = p;
                lt += p;
            }
            #pragma unroll
            for (int off = 1; off < 16; off <<= 1)
                lt += __shfl_xor_sync(0xffffffffu, lt, off);
            lrow[ii] = lrow[ii]*alpha + lt;
            mrow[ii] = mnew;
            u64 ad = dup2(alpha);
            mul2(o2[ii][0], ad);
            mul2(o2[ii][1], ad);
            // stash P row-major, vectorized (conflict-free STS.128)
            *(float4*)&Ps[(8*ty+ii)*68 + 4*tx] = make_float4(s[0], s[1], s[2], s[3]);
        }
        // Ps producer group == consumer group (threads 16*ty..16*ty+15, one
        // warp), so warp-level sync suffices; warps de-lockstep across iters.
        __syncwarp();

        // O += P @ V  (128x64x64): c chunked by 4 so P loads are LDS.128
        #pragma unroll 2
        for (int c0 = 0; c0 < 64; c0 += 4) {
            ulonglong2 vp[4];
            #pragma unroll
            for (int q = 0; q < 4; q++)
                vp[q] = *(const ulonglong2*)&Vs[(c0+q)*68 + 4*tx];
            #pragma unroll
            for (int ii = 0; ii < 8; ii++) {
                float4 p4 = *(const float4*)&Ps[(8*ty+ii)*68 + c0];
                float pr[4] = {p4.x, p4.y, p4.z, p4.w};
                #pragma unroll
                for (int q = 0; q < 4; q++) {
                    u64 pd = dup2(pr[q]);
                    fma2(o2[ii][0], pd, vp[q].x);
                    fma2(o2[ii][1], pd, vp[q].y);
                }
            }
        }
    }

    // normalize + write back into [b, s, d] interleaved layout
    #pragma unroll
    for (int ii = 0; ii < 8; ii++) {
        float inv = 1.0f / lrow[ii];
        int qr = qbase + 8*ty + ii;
        float2 oa = unp2(o2[ii][0]);
        float2 ob = unp2(o2[ii][1]);
        float* dst = g_ctx + ((size_t)(b*SEQ + qr))*DM + h*DK + 4*tx;
        *(float4*)dst = make_float4(oa.x*inv, oa.y*inv, ob.x*inv, ob.y*inv);
    }
}

// ---------------------------------------------------------------------------
extern "C" void kernel_launch(void* const* d_in, const int* in_sizes, int n_in,
                              void* d_out, int out_size)
{
    const float* x  = (const float*)d_in[0];
    const float* wq = (const float*)d_in[1];
    const float* bq = (const float*)d_in[2];
    const float* wk = (const float*)d_in[3];
    const float* bk = (const float*)d_in[4];
    const float* wv = (const float*)d_in[5];
    const float* bv = (const float*)d_in[6];
    const float* wo = (const float*)d_in[7];
    const float* bo = (const float*)d_in[8];

    float *qp, *kp, *vp, *cp;
    cudaGetSymbolAddress((void**)&qp, g_Q);
    cudaGetSymbolAddress((void**)&kp, g_K);
    cudaGetSymbolAddress((void**)&vp, g_V);
    cudaGetSymbolAddress((void**)&cp, g_ctx);

    cudaFuncSetAttribute(attn_kernel,
                         cudaFuncAttributeMaxDynamicSharedMemorySize, ATTN_SMEM);

    dim3 gq(DM/128, MTOT/128, 3);   // fused Q/K/V
    qkv_kernel<<<gq, 256>>>(x, wq, bq, qp, wk, bk, kp, wv, bv, vp);
    attn_kernel<<<dim3(SEQ/128, NH, BATCH), 256, ATTN_SMEM>>>();
    dim3 gg(DM/128, MTOT/128);
    gemm_kernel<false><<<gg, 256>>>(cp, wo, bo, (float*)d_out);
}